// round 5
// baseline (speedup 1.0000x reference)
#include <cuda_runtime.h>
#include <math.h>

// x is (B, F) row-major fp32
#define B_ROWS 32768
#define F_COLS 1024
#define F4     (F_COLS / 4)            // 256 float4 per row
#define NBLK   512                     // persistent grid (<= 148*4 resident)
#define ROWS_PER_CTA (B_ROWS / NBLK)   // 64
#define EPS 1e-5f

// Scratch (allocations forbidden)
__device__ float g_psum[NBLK * F_COLS];   // [chunk][col] partial sums   (2 MB)
__device__ float g_psqr[NBLK * F_COLS];   // [chunk][col] partial sumsq  (2 MB)
__device__ float g_mean[F_COLS];
__device__ float g_rstd[F_COLS];

// Grid barrier state (generation counter survives graph replays; equality
// test makes wraparound harmless).
__device__ unsigned g_count = 0;
__device__ volatile unsigned g_gen = 0;

__device__ __forceinline__ void grid_barrier(unsigned nblocks) {
    __syncthreads();
    if (threadIdx.x == 0) {
        unsigned gen = g_gen;                    // read BEFORE arriving
        __threadfence();                         // publish my phase's writes
        unsigned arrived = atomicAdd(&g_count, 1u) + 1u;
        if (arrived == nblocks) {
            atomicExch(&g_count, 0u);            // reset for next use
            __threadfence();
            g_gen = gen + 1u;                    // release
        } else {
            while (g_gen == gen) { __nanosleep(64); }
        }
        __threadfence();                         // acquire
    }
    __syncthreads();
}

// ---------------------------------------------------------------------------
// Fused persistent kernel.
// Phase 1: slice partial sums (forward, 8-deep batched float4 loads).
// Phase 2a: per-column mean/rstd (2 columns per CTA, scratch is L2-hot).
// Phase 2b: normalize own slice BACKWARD -> slice tail (read last in phase 1)
//           is L2/L1-hot. x reads .cs (dead after use, evict-first protects
//           other CTAs' unread lines); out stores .cs (streaming).
// ---------------------------------------------------------------------------
__global__ __launch_bounds__(256, 4) void msf_fused(const float* __restrict__ x,
                                                    const float* __restrict__ S_in,
                                                    float* __restrict__ out) {
    const int bid = blockIdx.x;
    const int t = threadIdx.x;
    const float4* __restrict__ x4 = reinterpret_cast<const float4*>(x);
    float4* __restrict__ o4 = reinterpret_cast<float4*>(out);

    // ---------------- Phase 1: partial sums over my 64-row slice ----------
    {
        float4 s = make_float4(0.f, 0.f, 0.f, 0.f);
        float4 q = make_float4(0.f, 0.f, 0.f, 0.f);
        const size_t base = (size_t)bid * ROWS_PER_CTA * F4 + t;

#pragma unroll
        for (int g = 0; g < ROWS_PER_CTA / 8; ++g) {
            float4 v[8];
#pragma unroll
            for (int j = 0; j < 8; ++j)
                v[j] = __ldg(&x4[base + (size_t)(g * 8 + j) * F4]);
#pragma unroll
            for (int j = 0; j < 8; ++j) {
                s.x += v[j].x; s.y += v[j].y; s.z += v[j].z; s.w += v[j].w;
                q.x = fmaf(v[j].x, v[j].x, q.x);
                q.y = fmaf(v[j].y, v[j].y, q.y);
                q.z = fmaf(v[j].z, v[j].z, q.z);
                q.w = fmaf(v[j].w, v[j].w, q.w);
            }
        }
        __stcs(&reinterpret_cast<float4*>(g_psum)[bid * F4 + t], s);
        __stcs(&reinterpret_cast<float4*>(g_psqr)[bid * F4 + t], q);
    }

    grid_barrier(NBLK);

    // ---------------- Phase 2a: stats for my 2 columns ---------------------
    {
        __shared__ float sh_s[256];
        __shared__ float sh_q[256];
        const int half = t >> 7;              // 0 or 1
        const int tt = t & 127;               // lane within half
        const int col = bid * 2 + half;

        float s = 0.f, q = 0.f;
#pragma unroll
        for (int k = 0; k < NBLK / 128; ++k) {      // 4 partials per thread
            const int c = k * 128 + tt;
            s += __ldcs(&g_psum[c * F_COLS + col]);
            q += __ldcs(&g_psqr[c * F_COLS + col]);
        }
        sh_s[t] = s; sh_q[t] = q;
        __syncthreads();
#pragma unroll
        for (int w = 64; w > 0; w >>= 1) {          // tree within each half
            if (tt < w) {
                sh_s[t] += sh_s[t + w];
                sh_q[t] += sh_q[t + w];
            }
            __syncthreads();
        }
        if (tt == 0) {
            const float n = (float)B_ROWS;
            float mean = sh_s[half << 7] / n;
            float m2 = sh_q[half << 7] - n * mean * mean + S_in[col];
            float var = m2 / (n - 1.0f);
            g_mean[col] = mean;
            g_rstd[col] = 1.0f / (sqrtf(var) + EPS);
        }
    }

    grid_barrier(NBLK);

    // ---------------- Phase 2b: normalize my slice, BACKWARD ---------------
    {
        const float4 m = __ldg(&reinterpret_cast<const float4*>(g_mean)[t]);
        const float4 r = __ldg(&reinterpret_cast<const float4*>(g_rstd)[t]);
        const size_t base = (size_t)bid * ROWS_PER_CTA * F4 + t;

#pragma unroll
        for (int g = ROWS_PER_CTA / 8 - 1; g >= 0; --g) {
            float4 v[8];
#pragma unroll
            for (int j = 0; j < 8; ++j)
                v[j] = __ldcs(&x4[base + (size_t)(g * 8 + j) * F4]);
#pragma unroll
            for (int j = 0; j < 8; ++j) {
                float4 o;
                o.x = (v[j].x - m.x) * r.x;
                o.y = (v[j].y - m.y) * r.y;
                o.z = (v[j].z - m.z) * r.z;
                o.w = (v[j].w - m.w) * r.w;
                __stcs(&o4[base + (size_t)(g * 8 + j) * F4], o);
            }
        }
    }
}

extern "C" void kernel_launch(void* const* d_in, const int* in_sizes, int n_in,
                              void* d_out, int out_size) {
    const float* x    = (const float*)d_in[0];   // (32768, 1024) fp32
    // d_in[1] = running-mean buffer M: overwritten by first Welford sample -> unused
    const float* S_in = (const float*)d_in[2];   // (1024,) running M2, added into var
    float* out = (float*)d_out;

    msf_fused<<<NBLK, 256>>>(x, S_in, out);
}